// round 14
// baseline (speedup 1.0000x reference)
#include <cuda_runtime.h>
#include <cuda_fp16.h>
#include <cstdint>

// Problem constants
constexpr int HID = 1024;
constexpr int NH  = 16;
constexpr int HD  = 64;
constexpr int B   = 2;
constexpr int S   = 2048;
constexpr int M   = B * S;

// ---------------------------------------------------------------------------
// Scratch (__device__ globals) — single fp16
// ---------------------------------------------------------------------------
__device__ __half g_xh[(size_t)M * HID];
__device__ __half g_wh[(size_t)4 * HID * HID];      // [Wq|Wk|Wv|Wo]
__device__ __half g_q [(size_t)M * HID];            // [B,H,S,D], *0.125*log2e
__device__ __half g_k [(size_t)M * HID];
__device__ __half g_v [(size_t)M * HID];
__device__ __half g_a [(size_t)M * HID];            // attn out [B,S,HID]

// ---------------------------------------------------------------------------
// PTX helpers
// ---------------------------------------------------------------------------
__device__ __forceinline__ uint32_t smem_u32(const void* p) {
    uint32_t a;
    asm("{ .reg .u64 t; cvta.to.shared.u64 t, %1; cvt.u32.u64 %0, t; }"
        : "=r"(a) : "l"(p));
    return a;
}

__device__ __forceinline__ void ldsm_x4(uint32_t (&r)[4], uint32_t addr) {
    asm volatile("ldmatrix.sync.aligned.m8n8.x4.shared.b16 {%0,%1,%2,%3}, [%4];"
                 : "=r"(r[0]), "=r"(r[1]), "=r"(r[2]), "=r"(r[3]) : "r"(addr));
}

__device__ __forceinline__ void ldsm_x4_t(uint32_t (&r)[4], uint32_t addr) {
    asm volatile("ldmatrix.sync.aligned.m8n8.x4.trans.shared.b16 {%0,%1,%2,%3}, [%4];"
                 : "=r"(r[0]), "=r"(r[1]), "=r"(r[2]), "=r"(r[3]) : "r"(addr));
}

__device__ __forceinline__ void ldsm_x2_t(uint32_t (&r)[2], uint32_t addr) {
    asm volatile("ldmatrix.sync.aligned.m8n8.x2.trans.shared.b16 {%0,%1}, [%2];"
                 : "=r"(r[0]), "=r"(r[1]) : "r"(addr));
}

__device__ __forceinline__ void mma_f16(float (&d)[4], const uint32_t (&a)[4],
                                        uint32_t b0, uint32_t b1) {
    asm volatile(
        "mma.sync.aligned.m16n8k16.row.col.f32.f16.f16.f32 "
        "{%0,%1,%2,%3}, {%4,%5,%6,%7}, {%8,%9}, {%0,%1,%2,%3};"
        : "+f"(d[0]), "+f"(d[1]), "+f"(d[2]), "+f"(d[3])
        : "r"(a[0]), "r"(a[1]), "r"(a[2]), "r"(a[3]), "r"(b0), "r"(b1));
}

__device__ __forceinline__ void cp16(uint32_t dst, const void* src) {
    asm volatile("cp.async.cg.shared.global [%0], [%1], 16;"
                 :: "r"(dst), "l"(src));
}
#define CP_COMMIT() asm volatile("cp.async.commit_group;")
#define CP_WAIT(n)  asm volatile("cp.async.wait_group %0;" :: "n"(n))

__device__ __forceinline__ uint32_t pack2f16(float a, float b) {
    __half2 h = __floats2half2_rn(a, b);
    return *reinterpret_cast<uint32_t*>(&h);
}

__device__ __forceinline__ uint32_t ex2_f16x2(uint32_t x) {
    uint32_t r;
    asm("ex2.approx.f16x2 %0, %1;" : "=r"(r) : "r"(x));
    return r;
}

// ---------------------------------------------------------------------------
// Pre-pass: one launch converts x AND all four W matrices to fp16.
// ---------------------------------------------------------------------------
constexpr int X_F4 = M * HID / 4;            // 1M float4
constexpr int W_F4 = HID * HID / 4;          // 256K float4 per W

__global__ __launch_bounds__(256)
void cvt_kernel(const float* __restrict__ x,
                const float* __restrict__ w0, const float* __restrict__ w1,
                const float* __restrict__ w2, const float* __restrict__ w3)
{
    const int gi = blockIdx.x * 256 + threadIdx.x;
    if (gi < X_F4) {
        float4 v = ((const float4*)x)[gi];
        ((uint2*)g_xh)[gi] = make_uint2(pack2f16(v.x, v.y), pack2f16(v.z, v.w));
    } else {
        const int wi  = gi - X_F4;
        const int sel = wi >> 18;
        const int i   = wi & ((1 << 18) - 1);
        const float* src = (sel == 0) ? w0 : (sel == 1) ? w1
                         : (sel == 2) ? w2 : w3;
        float4 v = ((const float4*)src)[i];
        ((uint2*)g_wh)[wi] = make_uint2(pack2f16(v.x, v.y), pack2f16(v.z, v.w));
    }
}

// ---------------------------------------------------------------------------
// GEMM v3: C = A @ W^T + bias. CTA tile 256x128, 8 warps in 4(M)x2(N) grid,
// 64x64 warp tiles (acc[4][8][4] = 128 regs), BK=32, 4-stage cp.async.
// ldsm/MMA ratio: 8 ldsm.x4 per 32 MMAs (was 6 per 16).
// IS_O=0: fused QKV (n over 3072) -> q (scaled 0.125*log2e) / k / v fp16.
// IS_O=1: O-projection from g_a; f32 output.
// ---------------------------------------------------------------------------
constexpr int G_AT    = 256 * 80;              // A tile: 20480 B
constexpr int G_WT    = 128 * 80;              // W tile: 10240 B
constexpr int G_STAGE = G_AT + G_WT;           // 30720 B
constexpr int G_SMEM  = 4 * G_STAGE;           // 122880 B (1 CTA/SM)

constexpr float QSCALE = 0.125f * 1.44269504088896f;   // 1/sqrt(64) * log2(e)

template <int IS_O>
__global__ __launch_bounds__(256)
void gemm_mma_kernel(const float* __restrict__ bq_,
                     const float* __restrict__ bk_,
                     const float* __restrict__ bv_,
                     float* __restrict__ Cout)
{
    extern __shared__ char dynsm[];
    const uint32_t smb = smem_u32(dynsm);

    const __half* A_g = IS_O ? g_a : g_xh;
    const __half* W_g = g_wh + (IS_O ? (size_t)3 * HID * HID : 0);

    const int t      = threadIdx.x;
    const int lane   = t & 31;
    const int wid    = t >> 5;
    const int warp_m = wid >> 1;     // 0..3 -> 64 rows
    const int warp_n = wid & 1;      // 0..1 -> 64 cols
    const int m0 = blockIdx.y * 256;
    const int n0 = blockIdx.x * 128;

    const int a_row = lane & 15;
    const int a_kb  = (lane >> 4) * 16;
    const int b_row = (lane & 7) + ((lane >> 4) << 3);
    const int b_kb  = ((lane >> 3) & 1) * 16;

    // loader: A 1024 + W 512 = 1536 16B-chunks per 32-k chunk; 6 per thread
    auto load_chunk = [&](int stage, int k0) {
#pragma unroll
        for (int it = 0; it < 6; it++) {
            const int i = t + it * 256;           // 0..1535
            if (i < 1024) {
                const int r = i >> 2;             // 0..255
                const int j = i & 3;
                cp16(smb + stage * G_STAGE + r * 80 + j * 16,
                     A_g + (size_t)(m0 + r) * HID + k0 + j * 8);
            } else {
                const int r = (i - 1024) >> 2;    // 0..127
                const int j = i & 3;
                cp16(smb + stage * G_STAGE + G_AT + r * 80 + j * 16,
                     W_g + (size_t)(n0 + r) * HID + k0 + j * 8);
            }
        }
    };

    float acc[4][8][4];
#pragma unroll
    for (int mt = 0; mt < 4; mt++)
#pragma unroll
        for (int nt = 0; nt < 8; nt++)
#pragma unroll
            for (int r = 0; r < 4; r++) acc[mt][nt][r] = 0.f;

    load_chunk(0, 0);   CP_COMMIT();
    load_chunk(1, 32);  CP_COMMIT();
    load_chunk(2, 64);  CP_COMMIT();

    for (int c = 0; c < 32; c++) {
        if (c < 30)      { CP_WAIT(2); }
        else if (c == 30){ CP_WAIT(1); }
        else             { CP_WAIT(0); }
        __syncthreads();
        if (c + 3 < 32) { load_chunk((c + 3) & 3, (c + 3) * 32); CP_COMMIT(); }

        const uint32_t sb = smb + (c & 3) * G_STAGE;
#pragma unroll
        for (int ks = 0; ks < 2; ks++) {
            const int ksb = ks * 32;

            uint32_t af[4][4];
#pragma unroll
            for (int mt = 0; mt < 4; mt++) {
                const uint32_t ro =
                    (uint32_t)((warp_m * 64 + mt * 16 + a_row) * 80 + ksb + a_kb);
                ldsm_x4(af[mt], sb + ro);
            }
            uint32_t bw[4][4];
#pragma unroll
            for (int bt = 0; bt < 4; bt++) {
                const uint32_t ro =
                    (uint32_t)((warp_n * 64 + bt * 16 + b_row) * 80 + ksb + b_kb);
                ldsm_x4(bw[bt], sb + G_AT + ro);
            }

#pragma unroll
            for (int mt = 0; mt < 4; mt++)
#pragma unroll
                for (int nt = 0; nt < 8; nt++) {
                    const int bt = nt >> 1;
                    const int hf = (nt & 1) * 2;
                    mma_f16(acc[mt][nt], af[mt], bw[bt][hf], bw[bt][hf + 1]);
                }
        }
    }

    // ---- epilogue ----
    const int fr = lane >> 2;
    const int fc = (lane & 3) * 2;
#pragma unroll
    for (int mt = 0; mt < 4; mt++)
#pragma unroll
        for (int nt = 0; nt < 8; nt++) {
            const int n_g = n0 + warp_n * 64 + nt * 8 + fc;
            float2 b2;
            float scl = 1.f;
            int w_idx = 0, n_w = n_g;
            if (!IS_O) {
                w_idx = n_g >> 10;
                n_w   = n_g & 1023;
                const float* bias = (w_idx == 0) ? bq_ : (w_idx == 1) ? bk_ : bv_;
                b2 = *(const float2*)&bias[n_w];
                if (w_idx == 0) scl = QSCALE;
            } else {
                b2 = *(const float2*)&bq_[n_g];
            }
#pragma unroll
            for (int p = 0; p < 2; p++) {
                const int m = m0 + warp_m * 64 + mt * 16 + fr + p * 8;
                const float vx = (acc[mt][nt][p * 2 + 0] + b2.x) * scl;
                const float vy = (acc[mt][nt][p * 2 + 1] + b2.y) * scl;
                if (!IS_O) {
                    const int bb = m >> 11;
                    const int ss = m & (S - 1);
                    const int hh = n_w >> 6;
                    const int dd = n_w & 63;
                    const size_t idx =
                        (((size_t)(bb * NH + hh) * S + ss) << 6) + dd;
                    __half* C = (w_idx == 0) ? g_q : (w_idx == 1) ? g_k : g_v;
                    *(uint32_t*)&C[idx] = pack2f16(vx, vy);
                } else {
                    float2 v; v.x = vx; v.y = vy;
                    *(float2*)&Cout[(size_t)m * HID + n_g] = v;
                }
            }
        }
}

// ---------------------------------------------------------------------------
// Attention (unchanged from R12): 256 threads, 8 warps, 128 q rows/CTA,
// 64-key tiles, 3-stage cp.async; base-2 softmax, P via ex2.approx.f16x2,
// row-sums via ones-column in the V-tile pad (oacc[8]).
// ---------------------------------------------------------------------------
constexpr int A_TILE  = 64 * 144;         // 9216 B
constexpr int A_STAGE = 2 * A_TILE;       // K | V = 18432 B
constexpr int A_SMEM  = 3 * A_STAGE;      // 55296 B -> 2 CTAs/SM

__global__ __launch_bounds__(256, 2)
void attn_mma_kernel()
{
    extern __shared__ char dynsm[];
    const uint32_t smb = smem_u32(dynsm);

    const int t    = threadIdx.x;
    const int lane = t & 31;
    const int w    = t >> 5;
    const int q0   = (gridDim.x - 1 - blockIdx.x) * 128;  // longest first
    const int bh   = blockIdx.y;
    const int bb   = bh >> 4;
    const int hh   = bh & 15;

    const size_t bh_off = (size_t)bh * S * HD;
    const __half* Kh_g = g_k + bh_off;
    const __half* Vh_g = g_v + bh_off;

    // ---- stage Q into stage0 area, pull fragments to registers ----
    {
#pragma unroll
        for (int it = 0; it < 4; it++) {
            const int i = t + it * 256;      // 0..1023 (16B chunks)
            const int r = i >> 3;            // 0..127
            const int j = i & 7;
            const size_t off = bh_off + (size_t)(q0 + r) * HD + j * 8;
            cp16(smb + r * 144 + j * 16, g_q + off);
        }
        CP_COMMIT();
        CP_WAIT(0);
        __syncthreads();
    }

    const int a_row = lane & 15;
    const int a_kb  = (lane >> 4) * 16;
    uint32_t qf[4][4];
#pragma unroll
    for (int ks = 0; ks < 4; ks++) {
        const uint32_t ro = (uint32_t)((w * 16 + a_row) * 144 + ks * 32 + a_kb);
        ldsm_x4(qf[ks], smb + ro);
    }

    // ---- init V-tile pad columns (ones column) once per stage ----
    {
        const uint32_t val = ((t & 3) == 0) ? pack2f16(1.f, 0.f) : 0u;
#pragma unroll
        for (int st = 0; st < 3; st++) {
            const uint32_t addr = smb + st * A_STAGE + A_TILE
                                + (t >> 2) * 144 + 128 + (t & 3) * 4;
            asm volatile("st.shared.b32 [%0], %1;" :: "r"(addr), "r"(val));
        }
    }
    __syncthreads();

    const int b_row = (lane & 7) + ((lane >> 4) << 3);
    const int b_kb  = ((lane >> 3) & 1) * 16;

    auto load_tile = [&](int stage, int k0) {
#pragma unroll
        for (int it = 0; it < 2; it++) {
            const int i = t + it * 256;   // 0..511
            const int r = i >> 3;         // 0..63
            const int j = i & 7;
            const size_t off = (size_t)(k0 + r) * HD + j * 8;
            const uint32_t d = smb + stage * A_STAGE + r * 144 + j * 16;
            cp16(d,          Kh_g + off);
            cp16(d + A_TILE, Vh_g + off);
        }
    };

    float m0 = -1e30f, m1 = -1e30f;
    float oacc[9][4];                      // [8] = ones-column sums (l)
#pragma unroll
    for (int nt = 0; nt < 9; nt++)
#pragma unroll
        for (int r = 0; r < 4; r++) oacc[nt][r] = 0.f;

    const int nk = q0 / 64 + 2;
    load_tile(0, 0);  CP_COMMIT();
    load_tile(1, 64); CP_COMMIT();

    for (int ki = 0; ki < nk; ki++) {
        const int k0 = ki * 64;
        if (ki + 1 < nk) { CP_WAIT(1); } else { CP_WAIT(0); }
        __syncthreads();
        if (ki + 2 < nk) { load_tile((ki + 2) % 3, k0 + 128); CP_COMMIT(); }

        const uint32_t sb = smb + (ki % 3) * A_STAGE;

        // ---- S = Q @ K^T (log2-domain scores) ----
        float sacc[8][4];
#pragma unroll
        for (int nt = 0; nt < 8; nt++)
#pragma unroll
            for (int r = 0; r < 4; r++) sacc[nt][r] = 0.f;

#pragma unroll
        for (int ks = 0; ks < 4; ks++) {
            uint32_t kh[4][4];
#pragma unroll
            for (int g = 0; g < 4; g++) {
                const uint32_t ro =
                    (uint32_t)((g * 16 + b_row) * 144 + ks * 32 + b_kb);
                ldsm_x4(kh[g], sb + ro);
            }
#pragma unroll
            for (int nt = 0; nt < 8; nt++) {
                const int g  = nt >> 1;
                const int hf = (nt & 1) * 2;
                mma_f16(sacc[nt], qf[ks], kh[g][hf], kh[g][hf + 1]);
            }
        }

        // ---- causal mask ----
        if (k0 >= q0) {
            const int grow = q0 + w * 16 + (lane >> 2);
#pragma unroll
            for (int nt = 0; nt < 8; nt++) {
                const int gc = k0 + nt * 8 + (lane & 3) * 2;
                if (gc     > grow)     sacc[nt][0] = -1e30f;
                if (gc + 1 > grow)     sacc[nt][1] = -1e30f;
                if (gc     > grow + 8) sacc[nt][2] = -1e30f;
                if (gc + 1 > grow + 8) sacc[nt][3] = -1e30f;
            }
        }

        // ---- online softmax (base-2): max reduce, P = ex2.f16x2 ----
        float mx0 = -1e30f, mx1 = -1e30f;
#pragma unroll
        for (int nt = 0; nt < 8; nt++) {
            mx0 = fmaxf(mx0, fmaxf(sacc[nt][0], sacc[nt][1]));
            mx1 = fmaxf(mx1, fmaxf(sacc[nt][2], sacc[nt][3]));
        }
        mx0 = fmaxf(mx0, __shfl_xor_sync(0xffffffffu, mx0, 1));
        mx0 = fmaxf(mx0, __shfl_xor_sync(0xffffffffu, mx0, 2));
        mx1 = fmaxf(mx1, __shfl_xor_sync(0xffffffffu, mx1, 1));
        mx1 = fmaxf(mx1, __shfl_xor_sync(0xffffffffu, mx1, 2));

        const float mn0 = fmaxf(m0, mx0);
        const float mn1 = fmaxf(m1, mx1);

        uint32_t pp[8][2];
#pragma unroll
        for (int nt = 0; nt < 8; nt++) {
            pp[nt][0] = ex2_f16x2(pack2f16(sacc[nt][0] - mn0,
                                           sacc[nt][1] - mn0));
            pp[nt][1] = ex2_f16x2(pack2f16(sacc[nt][2] - mn1,
                                           sacc[nt][3] - mn1));
        }

        const float sc0 = exp2f(m0 - mn0);
        const float sc1 = exp2f(m1 - mn1);
        m0 = mn0; m1 = mn1;
#pragma unroll
        for (int nt = 0; nt < 9; nt++) {
            oacc[nt][0] *= sc0; oacc[nt][1] *= sc0;
            oacc[nt][2] *= sc1; oacc[nt][3] *= sc1;
        }

        // ---- O += P @ V  (+ ones column -> row sums in oacc[8]) ----
#pragma unroll
        for (int ks = 0; ks < 4; ks++) {
            uint32_t ph[4];
            ph[0] = pp[2 * ks][0];
            ph[1] = pp[2 * ks][1];
            ph[2] = pp[2 * ks + 1][0];
            ph[3] = pp[2 * ks + 1][1];

            uint32_t vh[4][4];
#pragma unroll
            for (int g = 0; g < 4; g++) {
                const uint32_t ro =
                    (uint32_t)((ks * 16 + a_row) * 144 + g * 32 + a_kb);
                ldsm_x4_t(vh[g], sb + A_TILE + ro);
            }
            uint32_t vo[2];
            ldsm_x2_t(vo, sb + A_TILE
                          + (uint32_t)((ks * 16 + (lane & 15)) * 144 + 128));

#pragma unroll
            for (int nt = 0; nt < 8; nt++) {
                const int g  = nt >> 1;
                const int hf = (nt & 1) * 2;
                mma_f16(oacc[nt], ph, vh[g][hf], vh[g][hf + 1]);
            }
            mma_f16(oacc[8], ph, vo[0], vo[1]);
        }
    }

    // ---- finalize: l from ones-column, write fp16 to g_a [B,S,HID] ----
    const float l0 = __shfl_sync(0xffffffffu, oacc[8][0], lane & ~3);
    const float l1 = __shfl_sync(0xffffffffu, oacc[8][2], lane & ~3);
    const float il0 = 1.f / l0;
    const float il1 = 1.f / l1;
    const int r0 = q0 + w * 16 + (lane >> 2);
#pragma unroll
    for (int nt = 0; nt < 8; nt++) {
        const int d = nt * 8 + (lane & 3) * 2;
        const size_t i0 = ((size_t)bb * S + r0) * HID + hh * 64 + d;
        const size_t i1 = ((size_t)bb * S + r0 + 8) * HID + hh * 64 + d;
        *(uint32_t*)&g_a[i0] = pack2f16(oacc[nt][0] * il0, oacc[nt][1] * il0);
        *(uint32_t*)&g_a[i1] = pack2f16(oacc[nt][2] * il1, oacc[nt][3] * il1);
    }
}

// ---------------------------------------------------------------------------
// Launch
// ---------------------------------------------------------------------------
extern "C" void kernel_launch(void* const* d_in, const int* in_sizes, int n_in,
                              void* d_out, int out_size)
{
    const float* x  = (const float*)d_in[0];
    const float* Wq = (const float*)d_in[1];
    const float* bq = (const float*)d_in[2];
    const float* Wk = (const float*)d_in[3];
    const float* bk = (const float*)d_in[4];
    const float* Wv = (const float*)d_in[5];
    const float* bv = (const float*)d_in[6];
    const float* Wo = (const float*)d_in[7];
    const float* bo = (const float*)d_in[8];
    float* out = (float*)d_out;

    cudaFuncSetAttribute(attn_mma_kernel,
                         cudaFuncAttributeMaxDynamicSharedMemorySize, A_SMEM);
    cudaFuncSetAttribute(gemm_mma_kernel<0>,
                         cudaFuncAttributeMaxDynamicSharedMemorySize, G_SMEM);
    cudaFuncSetAttribute(gemm_mma_kernel<1>,
                         cudaFuncAttributeMaxDynamicSharedMemorySize, G_SMEM);

    cvt_kernel<<<(X_F4 + 4 * W_F4) / 256, 256>>>(x, Wq, Wk, Wv, Wo);

    // fused QKV: n spans 3*1024, m tiles of 256
    gemm_mma_kernel<0><<<dim3(24, 16), 256, G_SMEM>>>(bq, bk, bv, nullptr);

    attn_mma_kernel<<<dim3(S / 128, B * NH), 256, A_SMEM>>>();

    gemm_mma_kernel<1><<<dim3(8, 16), 256, G_SMEM>>>(bo, nullptr, nullptr, out);
}

// round 15
// speedup vs baseline: 1.1466x; 1.1466x over previous
#include <cuda_runtime.h>
#include <cuda_fp16.h>
#include <cstdint>

// Problem constants
constexpr int HID = 1024;
constexpr int NH  = 16;
constexpr int HD  = 64;
constexpr int B   = 2;
constexpr int S   = 2048;
constexpr int M   = B * S;

// ---------------------------------------------------------------------------
// Scratch (__device__ globals) — single fp16
// ---------------------------------------------------------------------------
__device__ __half g_xh[(size_t)M * HID];
__device__ __half g_wh[(size_t)4 * HID * HID];      // [Wq|Wk|Wv|Wo]
__device__ __half g_q [(size_t)M * HID];            // [B,H,S,D], *0.125*log2e
__device__ __half g_k [(size_t)M * HID];
__device__ __half g_v [(size_t)M * HID];
__device__ __half g_a [(size_t)M * HID];            // attn out [B,S,HID]

// ---------------------------------------------------------------------------
// PTX helpers
// ---------------------------------------------------------------------------
__device__ __forceinline__ uint32_t smem_u32(const void* p) {
    uint32_t a;
    asm("{ .reg .u64 t; cvta.to.shared.u64 t, %1; cvt.u32.u64 %0, t; }"
        : "=r"(a) : "l"(p));
    return a;
}

__device__ __forceinline__ void ldsm_x4(uint32_t (&r)[4], uint32_t addr) {
    asm volatile("ldmatrix.sync.aligned.m8n8.x4.shared.b16 {%0,%1,%2,%3}, [%4];"
                 : "=r"(r[0]), "=r"(r[1]), "=r"(r[2]), "=r"(r[3]) : "r"(addr));
}

__device__ __forceinline__ void ldsm_x4_t(uint32_t (&r)[4], uint32_t addr) {
    asm volatile("ldmatrix.sync.aligned.m8n8.x4.trans.shared.b16 {%0,%1,%2,%3}, [%4];"
                 : "=r"(r[0]), "=r"(r[1]), "=r"(r[2]), "=r"(r[3]) : "r"(addr));
}

__device__ __forceinline__ void ldsm_x2_t(uint32_t (&r)[2], uint32_t addr) {
    asm volatile("ldmatrix.sync.aligned.m8n8.x2.trans.shared.b16 {%0,%1}, [%2];"
                 : "=r"(r[0]), "=r"(r[1]) : "r"(addr));
}

__device__ __forceinline__ void mma_f16(float (&d)[4], const uint32_t (&a)[4],
                                        uint32_t b0, uint32_t b1) {
    asm volatile(
        "mma.sync.aligned.m16n8k16.row.col.f32.f16.f16.f32 "
        "{%0,%1,%2,%3}, {%4,%5,%6,%7}, {%8,%9}, {%0,%1,%2,%3};"
        : "+f"(d[0]), "+f"(d[1]), "+f"(d[2]), "+f"(d[3])
        : "r"(a[0]), "r"(a[1]), "r"(a[2]), "r"(a[3]), "r"(b0), "r"(b1));
}

__device__ __forceinline__ void cp16(uint32_t dst, const void* src) {
    asm volatile("cp.async.cg.shared.global [%0], [%1], 16;"
                 :: "r"(dst), "l"(src));
}
#define CP_COMMIT() asm volatile("cp.async.commit_group;")
#define CP_WAIT(n)  asm volatile("cp.async.wait_group %0;" :: "n"(n))

__device__ __forceinline__ uint32_t pack2f16(float a, float b) {
    __half2 h = __floats2half2_rn(a, b);
    return *reinterpret_cast<uint32_t*>(&h);
}

__device__ __forceinline__ uint32_t ex2_f16x2(uint32_t x) {
    uint32_t r;
    asm("ex2.approx.f16x2 %0, %1;" : "=r"(r) : "r"(x));
    return r;
}

// ---------------------------------------------------------------------------
// Pre-pass: one launch converts x AND all four W matrices to fp16.
// ---------------------------------------------------------------------------
constexpr int X_F4 = M * HID / 4;            // 1M float4
constexpr int W_F4 = HID * HID / 4;          // 256K float4 per W

__global__ __launch_bounds__(256)
void cvt_kernel(const float* __restrict__ x,
                const float* __restrict__ w0, const float* __restrict__ w1,
                const float* __restrict__ w2, const float* __restrict__ w3)
{
    const int gi = blockIdx.x * 256 + threadIdx.x;
    if (gi < X_F4) {
        float4 v = ((const float4*)x)[gi];
        ((uint2*)g_xh)[gi] = make_uint2(pack2f16(v.x, v.y), pack2f16(v.z, v.w));
    } else {
        const int wi  = gi - X_F4;
        const int sel = wi >> 18;
        const int i   = wi & ((1 << 18) - 1);
        const float* src = (sel == 0) ? w0 : (sel == 1) ? w1
                         : (sel == 2) ? w2 : w3;
        float4 v = ((const float4*)src)[i];
        ((uint2*)g_wh)[wi] = make_uint2(pack2f16(v.x, v.y), pack2f16(v.z, v.w));
    }
}

// ---------------------------------------------------------------------------
// GEMM (R12 config — best): 256 threads, warp grid 2(M)x4(N), 64x32 warp
// tiles, BK=64, 3-stage cp.async, one __syncthreads per 64-k chunk.
// IS_O=0: fused QKV (n over 3072) -> q (scaled 0.125*log2e) / k / v fp16.
// IS_O=1: O-projection from g_a; f32 output.
// ---------------------------------------------------------------------------
constexpr int G_TILE  = 128 * 144;     // 18432 B
constexpr int G_STAGE = 2 * G_TILE;    // 36864 B
constexpr int G_SMEM  = 3 * G_STAGE;   // 110592 B -> 2 CTAs/SM

constexpr float QSCALE = 0.125f * 1.44269504088896f;   // 1/sqrt(64) * log2(e)

template <int IS_O>
__global__ __launch_bounds__(256, 2)
void gemm_mma_kernel(const float* __restrict__ bq_,
                     const float* __restrict__ bk_,
                     const float* __restrict__ bv_,
                     float* __restrict__ Cout)
{
    extern __shared__ char dynsm[];
    const uint32_t smb = smem_u32(dynsm);

    const __half* A_g = IS_O ? g_a : g_xh;
    const __half* W_g = g_wh + (IS_O ? (size_t)3 * HID * HID : 0);

    const int t      = threadIdx.x;
    const int lane   = t & 31;
    const int wid    = t >> 5;
    const int warp_m = wid >> 2;
    const int warp_n = wid & 3;
    const int m0 = blockIdx.y * 128;
    const int n0 = blockIdx.x * 128;

    const int a_row = lane & 15;
    const int a_kb  = (lane >> 4) * 16;
    const int b_row = (lane & 7) + ((lane >> 4) << 3);
    const int b_kb  = ((lane >> 3) & 1) * 16;

    const int lr = t >> 3;
    const int lj = t & 7;

    auto load_chunk = [&](int stage, int k0) {
#pragma unroll
        for (int it = 0; it < 4; it++) {
            const int r = lr + it * 32;
            const size_t aoff = (size_t)(m0 + r) * HID + k0 + lj * 8;
            const size_t woff = (size_t)(n0 + r) * HID + k0 + lj * 8;
            const uint32_t d = smb + stage * G_STAGE + r * 144 + lj * 16;
            cp16(d,          A_g + aoff);
            cp16(d + G_TILE, W_g + woff);
        }
    };

    float acc[4][4][4];
#pragma unroll
    for (int mt = 0; mt < 4; mt++)
#pragma unroll
        for (int nt = 0; nt < 4; nt++)
#pragma unroll
            for (int r = 0; r < 4; r++) acc[mt][nt][r] = 0.f;

    load_chunk(0, 0);   CP_COMMIT();
    load_chunk(1, 64);  CP_COMMIT();

    for (int c = 0; c < 16; c++) {
        if (c + 1 < 16) { CP_WAIT(1); } else { CP_WAIT(0); }
        __syncthreads();
        if (c + 2 < 16) { load_chunk((c + 2) % 3, (c + 2) * 64); CP_COMMIT(); }

        const uint32_t sb = smb + (c % 3) * G_STAGE;
#pragma unroll
        for (int ks = 0; ks < 4; ks++) {
            const int ksb = ks * 32;

            uint32_t af[4][4];
#pragma unroll
            for (int mt = 0; mt < 4; mt++) {
                const uint32_t ro =
                    (uint32_t)((warp_m * 64 + mt * 16 + a_row) * 144 + ksb + a_kb);
                ldsm_x4(af[mt], sb + ro);
            }
            uint32_t bw[2][4];
#pragma unroll
            for (int bt = 0; bt < 2; bt++) {
                const uint32_t ro =
                    (uint32_t)((warp_n * 32 + bt * 16 + b_row) * 144 + ksb + b_kb);
                ldsm_x4(bw[bt], sb + G_TILE + ro);
            }

#pragma unroll
            for (int mt = 0; mt < 4; mt++)
#pragma unroll
                for (int nt = 0; nt < 4; nt++) {
                    const int bt = nt >> 1;
                    const int hf = (nt & 1) * 2;
                    mma_f16(acc[mt][nt], af[mt], bw[bt][hf], bw[bt][hf + 1]);
                }
        }
    }

    // ---- epilogue ----
    const int fr = lane >> 2;
    const int fc = (lane & 3) * 2;
#pragma unroll
    for (int mt = 0; mt < 4; mt++)
#pragma unroll
        for (int nt = 0; nt < 4; nt++) {
            const int n_g = n0 + warp_n * 32 + nt * 8 + fc;
            float2 b2;
            float scl = 1.f;
            int w_idx = 0, n_w = n_g;
            if (!IS_O) {
                w_idx = n_g >> 10;
                n_w   = n_g & 1023;
                const float* bias = (w_idx == 0) ? bq_ : (w_idx == 1) ? bk_ : bv_;
                b2 = *(const float2*)&bias[n_w];
                if (w_idx == 0) scl = QSCALE;
            } else {
                b2 = *(const float2*)&bq_[n_g];
            }
#pragma unroll
            for (int p = 0; p < 2; p++) {
                const int m = m0 + warp_m * 64 + mt * 16 + fr + p * 8;
                const float vx = (acc[mt][nt][p * 2 + 0] + b2.x) * scl;
                const float vy = (acc[mt][nt][p * 2 + 1] + b2.y) * scl;
                if (!IS_O) {
                    const int bb = m >> 11;
                    const int ss = m & (S - 1);
                    const int hh = n_w >> 6;
                    const int dd = n_w & 63;
                    const size_t idx =
                        (((size_t)(bb * NH + hh) * S + ss) << 6) + dd;
                    __half* C = (w_idx == 0) ? g_q : (w_idx == 1) ? g_k : g_v;
                    *(uint32_t*)&C[idx] = pack2f16(vx, vy);
                } else {
                    float2 v; v.x = vx; v.y = vy;
                    *(float2*)&Cout[(size_t)m * HID + n_g] = v;
                }
            }
        }
}

// ---------------------------------------------------------------------------
// Attention (R12 + warp-level causal tile skip): 256 threads, 8 warps,
// 128 q rows/CTA, 64-key tiles, 3-stage cp.async; base-2 softmax,
// P via ex2.approx.f16x2, row-sums via ones-column in V-tile pad.
// A warp skips a tile entirely when all its 16 q-rows are below every key
// in the tile (k0 >= q0 + w*16 + 16) — contributes exactly nothing.
// ---------------------------------------------------------------------------
constexpr int A_TILE  = 64 * 144;         // 9216 B
constexpr int A_STAGE = 2 * A_TILE;       // K | V = 18432 B
constexpr int A_SMEM  = 3 * A_STAGE;      // 55296 B -> 2 CTAs/SM

__global__ __launch_bounds__(256, 2)
void attn_mma_kernel()
{
    extern __shared__ char dynsm[];
    const uint32_t smb = smem_u32(dynsm);

    const int t    = threadIdx.x;
    const int lane = t & 31;
    const int w    = t >> 5;
    const int q0   = (gridDim.x - 1 - blockIdx.x) * 128;  // longest first
    const int bh   = blockIdx.y;
    const int bb   = bh >> 4;
    const int hh   = bh & 15;

    const size_t bh_off = (size_t)bh * S * HD;
    const __half* Kh_g = g_k + bh_off;
    const __half* Vh_g = g_v + bh_off;

    // ---- stage Q into stage0 area, pull fragments to registers ----
    {
#pragma unroll
        for (int it = 0; it < 4; it++) {
            const int i = t + it * 256;      // 0..1023 (16B chunks)
            const int r = i >> 3;            // 0..127
            const int j = i & 7;
            const size_t off = bh_off + (size_t)(q0 + r) * HD + j * 8;
            cp16(smb + r * 144 + j * 16, g_q + off);
        }
        CP_COMMIT();
        CP_WAIT(0);
        __syncthreads();
    }

    const int a_row = lane & 15;
    const int a_kb  = (lane >> 4) * 16;
    uint32_t qf[4][4];
#pragma unroll
    for (int ks = 0; ks < 4; ks++) {
        const uint32_t ro = (uint32_t)((w * 16 + a_row) * 144 + ks * 32 + a_kb);
        ldsm_x4(qf[ks], smb + ro);
    }

    // ---- init V-tile pad columns (ones column) once per stage ----
    {
        const uint32_t val = ((t & 3) == 0) ? pack2f16(1.f, 0.f) : 0u;
#pragma unroll
        for (int st = 0; st < 3; st++) {
            const uint32_t addr = smb + st * A_STAGE + A_TILE
                                + (t >> 2) * 144 + 128 + (t & 3) * 4;
            asm volatile("st.shared.b32 [%0], %1;" :: "r"(addr), "r"(val));
        }
    }
    __syncthreads();

    const int b_row = (lane & 7) + ((lane >> 4) << 3);
    const int b_kb  = ((lane >> 3) & 1) * 16;

    auto load_tile = [&](int stage, int k0) {
#pragma unroll
        for (int it = 0; it < 2; it++) {
            const int i = t + it * 256;   // 0..511
            const int r = i >> 3;         // 0..63
            const int j = i & 7;
            const size_t off = (size_t)(k0 + r) * HD + j * 8;
            const uint32_t d = smb + stage * A_STAGE + r * 144 + j * 16;
            cp16(d,          Kh_g + off);
            cp16(d + A_TILE, Vh_g + off);
        }
    };

    float m0 = -1e30f, m1 = -1e30f;
    float oacc[9][4];                      // [8] = ones-column sums (l)
#pragma unroll
    for (int nt = 0; nt < 9; nt++)
#pragma unroll
        for (int r = 0; r < 4; r++) oacc[nt][r] = 0.f;

    const int nk = q0 / 64 + 2;
    load_tile(0, 0);  CP_COMMIT();
    load_tile(1, 64); CP_COMMIT();

    for (int ki = 0; ki < nk; ki++) {
        const int k0 = ki * 64;
        if (ki + 1 < nk) { CP_WAIT(1); } else { CP_WAIT(0); }
        __syncthreads();
        if (ki + 2 < nk) { load_tile((ki + 2) % 3, k0 + 128); CP_COMMIT(); }

        // Warp-level causal skip: tile entirely in this warp's future.
        if (k0 >= q0 + w * 16 + 16) continue;

        const uint32_t sb = smb + (ki % 3) * A_STAGE;

        // ---- S = Q @ K^T (log2-domain scores) ----
        float sacc[8][4];
#pragma unroll
        for (int nt = 0; nt < 8; nt++)
#pragma unroll
            for (int r = 0; r < 4; r++) sacc[nt][r] = 0.f;

#pragma unroll
        for (int ks = 0; ks < 4; ks++) {
            uint32_t kh[4][4];
#pragma unroll
            for (int g = 0; g < 4; g++) {
                const uint32_t ro =
                    (uint32_t)((g * 16 + b_row) * 144 + ks * 32 + b_kb);
                ldsm_x4(kh[g], sb + ro);
            }
#pragma unroll
            for (int nt = 0; nt < 8; nt++) {
                const int g  = nt >> 1;
                const int hf = (nt & 1) * 2;
                mma_f16(sacc[nt], qf[ks], kh[g][hf], kh[g][hf + 1]);
            }
        }

        // ---- causal mask ----
        if (k0 >= q0) {
            const int grow = q0 + w * 16 + (lane >> 2);
#pragma unroll
            for (int nt = 0; nt < 8; nt++) {
                const int gc = k0 + nt * 8 + (lane & 3) * 2;
                if (gc     > grow)     sacc[nt][0] = -1e30f;
                if (gc + 1 > grow)     sacc[nt][1] = -1e30f;
                if (gc     > grow + 8) sacc[nt][2] = -1e30f;
                if (gc + 1 > grow + 8) sacc[nt][3] = -1e30f;
            }
        }

        // ---- online softmax (base-2): max reduce, P = ex2.f16x2 ----
        float mx0 = -1e30f, mx1 = -1e30f;
#pragma unroll
        for (int nt = 0; nt < 8; nt++) {
            mx0 = fmaxf(mx0, fmaxf(sacc[nt][0], sacc[nt][1]));
            mx1 = fmaxf(mx1, fmaxf(sacc[nt][2], sacc[nt][3]));
        }
        mx0 = fmaxf(mx0, __shfl_xor_sync(0xffffffffu, mx0, 1));
        mx0 = fmaxf(mx0, __shfl_xor_sync(0xffffffffu, mx0, 2));
        mx1 = fmaxf(mx1, __shfl_xor_sync(0xffffffffu, mx1, 1));
        mx1 = fmaxf(mx1, __shfl_xor_sync(0xffffffffu, mx1, 2));

        const float mn0 = fmaxf(m0, mx0);
        const float mn1 = fmaxf(m1, mx1);

        uint32_t pp[8][2];
#pragma unroll
        for (int nt = 0; nt < 8; nt++) {
            pp[nt][0] = ex2_f16x2(pack2f16(sacc[nt][0] - mn0,
                                           sacc[nt][1] - mn0));
            pp[nt][1] = ex2_f16x2(pack2f16(sacc[nt][2] - mn1,
                                           sacc[nt][3] - mn1));
        }

        const float sc0 = exp2f(m0 - mn0);
        const float sc1 = exp2f(m1 - mn1);
        m0 = mn0; m1 = mn1;
#pragma unroll
        for (int nt = 0; nt < 9; nt++) {
            oacc[nt][0] *= sc0; oacc[nt][1] *= sc0;
            oacc[nt][2] *= sc1; oacc[nt][3] *= sc1;
        }

        // ---- O += P @ V  (+ ones column -> row sums in oacc[8]) ----
#pragma unroll
        for (int ks = 0; ks < 4; ks++) {
            uint32_t ph[4];
            ph[0] = pp[2 * ks][0];
            ph[1] = pp[2 * ks][1];
            ph[2] = pp[2 * ks + 1][0];
            ph[3] = pp[2 * ks + 1][1];

            uint32_t vh[4][4];
#pragma unroll
            for (int g = 0; g < 4; g++) {
                const uint32_t ro =
                    (uint32_t)((ks * 16 + a_row) * 144 + g * 32 + a_kb);
                ldsm_x4_t(vh[g], sb + A_TILE + ro);
            }
            uint32_t vo[2];
            ldsm_x2_t(vo, sb + A_TILE
                          + (uint32_t)((ks * 16 + (lane & 15)) * 144 + 128));

#pragma unroll
            for (int nt = 0; nt < 8; nt++) {
                const int g  = nt >> 1;
                const int hf = (nt & 1) * 2;
                mma_f16(oacc[nt], ph, vh[g][hf], vh[g][hf + 1]);
            }
            mma_f16(oacc[8], ph, vo[0], vo[1]);
        }
    }

    // ---- finalize: l from ones-column, write fp16 to g_a [B,S,HID] ----
    const float l0 = __shfl_sync(0xffffffffu, oacc[8][0], lane & ~3);
    const float l1 = __shfl_sync(0xffffffffu, oacc[8][2], lane & ~3);
    const float il0 = 1.f / l0;
    const float il1 = 1.f / l1;
    const int r0 = q0 + w * 16 + (lane >> 2);
#pragma unroll
    for (int nt = 0; nt < 8; nt++) {
        const int d = nt * 8 + (lane & 3) * 2;
        const size_t i0 = ((size_t)bb * S + r0) * HID + hh * 64 + d;
        const size_t i1 = ((size_t)bb * S + r0 + 8) * HID + hh * 64 + d;
        *(uint32_t*)&g_a[i0] = pack2f16(oacc[nt][0] * il0, oacc[nt][1] * il0);
        *(uint32_t*)&g_a[i1] = pack2f16(oacc[nt][2] * il1, oacc[nt][3] * il1);
    }
}

// ---------------------------------------------------------------------------
// Launch
// ---------------------------------------------------------------------------
extern "C" void kernel_launch(void* const* d_in, const int* in_sizes, int n_in,
                              void* d_out, int out_size)
{
    const float* x  = (const float*)d_in[0];
    const float* Wq = (const float*)d_in[1];
    const float* bq = (const float*)d_in[2];
    const float* Wk = (const float*)d_in[3];
    const float* bk = (const float*)d_in[4];
    const float* Wv = (const float*)d_in[5];
    const float* bv = (const float*)d_in[6];
    const float* Wo = (const float*)d_in[7];
    const float* bo = (const float*)d_in[8];
    float* out = (float*)d_out;

    cudaFuncSetAttribute(attn_mma_kernel,
                         cudaFuncAttributeMaxDynamicSharedMemorySize, A_SMEM);
    cudaFuncSetAttribute(gemm_mma_kernel<0>,
                         cudaFuncAttributeMaxDynamicSharedMemorySize, G_SMEM);
    cudaFuncSetAttribute(gemm_mma_kernel<1>,
                         cudaFuncAttributeMaxDynamicSharedMemorySize, G_SMEM);

    cvt_kernel<<<(X_F4 + 4 * W_F4) / 256, 256>>>(x, Wq, Wk, Wv, Wo);

    // fused QKV: n spans 3*1024
    gemm_mma_kernel<0><<<dim3(24, 32), 256, G_SMEM>>>(bq, bk, bv, nullptr);

    attn_mma_kernel<<<dim3(S / 128, B * NH), 256, A_SMEM>>>();

    gemm_mma_kernel<1><<<dim3(8, 32), 256, G_SMEM>>>(bo, nullptr, nullptr, out);
}